// round 16
// baseline (speedup 1.0000x reference)
#include <cuda_runtime.h>
#include <cuda_fp16.h>
#include <math.h>
#include <stdint.h>

// ---------------------------------------------------------------------------
// Problem constants: B=4, L=1024, DH=2048, D=128, HQ=16, HK=HV=4, H=16, K=4
// ---------------------------------------------------------------------------
#define ROWS 4096
#define DH_  2048
#define DHEAD 128
#define NH   16
#define NHK  4
#define SEQ  1024
#define NCAT 5120
#define COL_K 2048
#define COL_V 2560
#define COL_G 3072

// ---------------- device scratch (allocation-free rule) --------------------
__device__ float g_xcat[ROWS * NCAT];
__device__ float g_q [ROWS * DH_];
__device__ float g_k [ROWS * 512];
__device__ float g_v [ROWS * 512];
__device__ float g_beta[ROWS * NH];
__device__ float g_gd  [ROWS * NH];      // log decay g (<= 0)
__device__ float g_o [ROWS * DH_];

__device__ __align__(256) __half g_xhi[ROWS * DH_];
__device__ __align__(256) __half g_of [ROWS * DH_];
__device__ __align__(256) __half g_wcat[NCAT * DH_];
__device__ __align__(256) __half g_wot[DH_ * DH_];

// ---------------------------------------------------------------------------
// PTX helpers
// ---------------------------------------------------------------------------
__device__ __forceinline__ uint32_t smem_to_u32(const void* p) {
    uint32_t a;
    asm("{ .reg .u64 t; cvta.to.shared.u64 t, %1; cvt.u32.u64 %0, t; }"
        : "=r"(a) : "l"(p));
    return a;
}
__device__ __forceinline__ void cp16(uint32_t s, const void* g) {
    asm volatile("cp.async.cg.shared.global [%0], [%1], 16;"
                 :: "r"(s), "l"(g) : "memory");
}
#define CP_COMMIT() asm volatile("cp.async.commit_group;" ::: "memory")

#define LDSM4(d, addr) \
    asm volatile("ldmatrix.sync.aligned.m8n8.x4.shared.b16 {%0,%1,%2,%3}, [%4];" \
        : "=r"((d)[0]), "=r"((d)[1]), "=r"((d)[2]), "=r"((d)[3]) : "r"(addr))

#define LDSM2(d, addr) \
    asm volatile("ldmatrix.sync.aligned.m8n8.x2.shared.b16 {%0,%1}, [%2];" \
        : "=r"((d)[0]), "=r"((d)[1]) : "r"(addr))

#define MMA16816F(c, a, b) \
    asm volatile("mma.sync.aligned.m16n8k16.row.col.f32.f16.f16.f32 " \
        "{%0,%1,%2,%3}, {%4,%5,%6,%7}, {%8,%9}, {%0,%1,%2,%3};" \
        : "+f"((c)[0]), "+f"((c)[1]), "+f"((c)[2]), "+f"((c)[3]) \
        : "r"((a)[0]), "r"((a)[1]), "r"((a)[2]), "r"((a)[3]), \
          "r"((b)[0]), "r"((b)[1]))

// pack 4 floats -> 4 fp16 in a uint2 ; and hi/lo split of a float4
__device__ __forceinline__ uint2 pack4h(float a, float b, float c, float d) {
    __half2 p0 = __halves2half2(__float2half_rn(a), __float2half_rn(b));
    __half2 p1 = __halves2half2(__float2half_rn(c), __float2half_rn(d));
    uint2 u;
    u.x = *(uint32_t*)&p0;
    u.y = *(uint32_t*)&p1;
    return u;
}
__device__ __forceinline__ void split4(float4 v, uint2& hi, uint2& lo) {
    __half h0 = __float2half_rn(v.x), h1 = __float2half_rn(v.y);
    __half h2 = __float2half_rn(v.z), h3 = __float2half_rn(v.w);
    hi = pack4h(v.x, v.y, v.z, v.w);
    lo = pack4h(v.x - __half2float(h0), v.y - __half2float(h1),
                v.z - __half2float(h2), v.w - __half2float(h3));
}

// ---------------------------------------------------------------------------
// prep: blocks [0,16384) x->fp16 ; [16384,30720) weight transposes
// ---------------------------------------------------------------------------
#define PREP_T0 16384
#define PREP_NB 30720

__global__ __launch_bounds__(256) void prep_kernel(
    const float* __restrict__ x,
    const float* __restrict__ Wq, const float* __restrict__ Wk,
    const float* __restrict__ Wv, const float* __restrict__ Wg,
    const float* __restrict__ Wo,
    __half* __restrict__ xhi, __half* __restrict__ wcat, __half* __restrict__ wot)
{
    __shared__ float t[32][33];
    const int blk = blockIdx.x;
    const int tid = threadIdx.x;

    if (blk < PREP_T0) {
        int i = blk * 256 + tid;
        float2 v = ((const float2*)x)[i];
        ((__half2*)xhi)[i] = __halves2half2(__float2half_rn(v.x), __float2half_rn(v.y));
        return;
    }
    const int idx = blk - PREP_T0;
    const float* W; __half* T; int N, bx, by;
    if (idx < 4096)        { W = Wq; T = wcat;                        N = 2048; int l = idx;         bx = l & 63; by = l >> 6; }
    else if (idx < 5120)   { W = Wk; T = wcat + (size_t)COL_K * DH_;  N =  512; int l = idx - 4096;  bx = l & 15; by = l >> 4; }
    else if (idx < 6144)   { W = Wv; T = wcat + (size_t)COL_V * DH_;  N =  512; int l = idx - 5120;  bx = l & 15; by = l >> 4; }
    else if (idx < 10240)  { W = Wg; T = wcat + (size_t)COL_G * DH_;  N = 2048; int l = idx - 6144;  bx = l & 63; by = l >> 6; }
    else                   { W = Wo; T = wot;                         N = 2048; int l = idx - 10240; bx = l & 63; by = l >> 6; }
    bx <<= 5; by <<= 5;
    const int tx = tid & 31, ty = tid >> 5;
    #pragma unroll
    for (int i = 0; i < 32; i += 8)
        t[ty + i][tx] = W[(size_t)(by + ty + i) * N + bx + tx];
    __syncthreads();
    #pragma unroll
    for (int i = 0; i < 32; i += 8)
        T[(size_t)(bx + ty + i) * DH_ + by + tx] = __float2half_rn(t[tx][ty + i]);
}

// ---------------------------------------------------------------------------
// 1-pass fp16 GEMM (proven): C = A @ B^T
// ---------------------------------------------------------------------------
#define ST1 32768
#define SM1 (3 * ST1)

__global__ __launch_bounds__(256, 2) void gemm1(
    const __half* __restrict__ A, const __half* __restrict__ B,
    float* __restrict__ C, int N, int K)
{
    extern __shared__ char smem[];
    const uint32_t sb = smem_to_u32(smem);
    const int tid  = threadIdx.x;
    const int lane = tid & 31;
    const int wid  = tid >> 5;
    const int wm   = wid & 1;
    const int wn   = wid >> 1;
    const int brow = blockIdx.y * 128;
    const int bcol = blockIdx.x * 128;
    const size_t K2 = (size_t)K * 2;

    uint32_t swo[4];
    size_t   ga[4], gb[4];
    #pragma unroll
    for (int i = 0; i < 4; i++) {
        int c  = tid + (i << 8);
        int r  = c >> 3, ch = c & 7;
        swo[i] = (uint32_t)(r * 128 + ((ch ^ (r & 7)) << 4));
        ga[i]  = (size_t)(brow + r) * K2 + (size_t)(ch << 4);
        gb[i]  = (size_t)(bcol + r) * K2 + (size_t)(ch << 4);
    }

    const int NK = K >> 6;
    #pragma unroll
    for (int pf = 0; pf < 2; pf++) {
        uint32_t s0 = sb + pf * ST1;
        size_t ko = (size_t)pf << 7;
        #pragma unroll
        for (int i = 0; i < 4; i++) {
            cp16(s0 +     0 + swo[i], (const char*)A + ga[i] + ko);
            cp16(s0 + 16384 + swo[i], (const char*)B + gb[i] + ko);
        }
        CP_COMMIT();
    }

    float acc[4][4][4];
    #pragma unroll
    for (int mi = 0; mi < 4; mi++)
        #pragma unroll
        for (int ni = 0; ni < 4; ni++)
            #pragma unroll
            for (int j = 0; j < 4; j++) acc[mi][ni][j] = 0.f;

    int st_load = 2, st_cmp = 0;
    for (int kt = 0; kt < NK; kt++) {
        if (kt + 2 < NK) {
            uint32_t s0 = sb + st_load * ST1;
            size_t ko = (size_t)(kt + 2) << 7;
            #pragma unroll
            for (int i = 0; i < 4; i++) {
                cp16(s0 +     0 + swo[i], (const char*)A + ga[i] + ko);
                cp16(s0 + 16384 + swo[i], (const char*)B + gb[i] + ko);
            }
            CP_COMMIT();
            if (++st_load == 3) st_load = 0;
        }
        int ahead = NK - 1 - kt; if (ahead > 2) ahead = 2;
        if (ahead == 2)      asm volatile("cp.async.wait_group 2;" ::: "memory");
        else if (ahead == 1) asm volatile("cp.async.wait_group 1;" ::: "memory");
        else                 asm volatile("cp.async.wait_group 0;" ::: "memory");
        __syncthreads();

        const uint32_t sa = sb + st_cmp * ST1;
        #pragma unroll
        for (int ks = 0; ks < 4; ks++) {
            uint32_t ah[4][4];
            const int chA = (ks << 1) + (lane >> 4);
            #pragma unroll
            for (int mi = 0; mi < 4; mi++) {
                int r = wm * 64 + mi * 16 + (lane & 15);
                uint32_t ad = sa + (uint32_t)(r * 128 + ((chA ^ (r & 7)) << 4));
                LDSM4(ah[mi], ad);
            }
            uint32_t bh[4][2];
            #pragma unroll
            for (int nb = 0; nb < 2; nb++) {
                int r = wn * 32 + nb * 16 + (lane & 15);
                uint32_t bd = sa + 16384u + (uint32_t)(r * 128 + ((chA ^ (r & 7)) << 4));
                uint32_t d[4];
                LDSM4(d, bd);
                bh[2*nb][0] = d[0];   bh[2*nb][1] = d[2];
                bh[2*nb+1][0] = d[1]; bh[2*nb+1][1] = d[3];
            }
            #pragma unroll
            for (int mi = 0; mi < 4; mi++)
                #pragma unroll
                for (int ni = 0; ni < 4; ni++)
                    MMA16816F(acc[mi][ni], ah[mi], bh[ni]);
        }
        __syncthreads();
        if (++st_cmp == 3) st_cmp = 0;
    }

    #pragma unroll
    for (int mi = 0; mi < 4; mi++) {
        int r0 = brow + wm * 64 + mi * 16 + (lane >> 2);
        #pragma unroll
        for (int ni = 0; ni < 4; ni++) {
            int c0 = bcol + wn * 32 + ni * 8 + ((lane & 3) << 1);
            *(float2*)&C[(size_t)r0 * N + c0] =
                make_float2(acc[mi][ni][0], acc[mi][ni][1]);
            *(float2*)&C[(size_t)(r0 + 8) * N + c0] =
                make_float2(acc[mi][ni][2], acc[mi][ni][3]);
        }
    }
}

// ---------------------------------------------------------------------------
// conv + betag: grid (4096, 25). y==24: beta / g (log decay, fp32 exact)
// ---------------------------------------------------------------------------
__global__ __launch_bounds__(128) void conv_betag(
    const float* __restrict__ xcat, const float* __restrict__ x,
    const float* __restrict__ wq, const float* __restrict__ wk,
    const float* __restrict__ wv,
    const float* __restrict__ Wb, const float* __restrict__ Wgk,
    const float* __restrict__ A_log, const float* __restrict__ dt_bias)
{
    __shared__ float xs[DH_];
    const int row = blockIdx.x;
    const int y   = blockIdx.y;
    const int tid = threadIdx.x;

    if (y == 24) {
        const float4* xin = (const float4*)(x + (size_t)row * DH_);
        float4* xs4 = (float4*)xs;
        for (int i = tid; i < DH_ / 4; i += 128) xs4[i] = xin[i];
        __syncthreads();
        const int o = tid >> 2;
        const int j = tid & 3;
        const int col = o & 15;
        const float* W = (o < 16) ? Wb : Wgk;
        float s = 0.f;
        #pragma unroll 4
        for (int k = j; k < DH_; k += 4)
            s = fmaf(xs[k], W[k * NH + col], s);
        s += __shfl_xor_sync(0xffffffffu, s, 1);
        s += __shfl_xor_sync(0xffffffffu, s, 2);
        if (j == 0) {
            if (o < 16) {
                g_beta[row * NH + col] = 1.f / (1.f + expf(-s));
            } else {
                float xg = s + dt_bias[col];
                float sp = (xg > 15.f) ? xg : log1pf(expf(xg));
                g_gd[row * NH + col] = -expf(A_log[col]) * sp;   // log decay
            }
        }
        return;
    }

    const int l = row & (SEQ - 1);
    const float* in; const float* w; float* out;
    int c, chans, do_l2; float scale;
    if (y < 16)      { c = y * DHEAD + tid;        in = xcat;         w = wq; out = g_q; chans = 2048; do_l2 = 1; scale = 0.08838834764831845f; }
    else if (y < 20) { c = (y - 16) * DHEAD + tid; in = xcat + COL_K; w = wk; out = g_k; chans = 512;  do_l2 = 1; scale = 1.f; }
    else             { c = (y - 20) * DHEAD + tid; in = xcat + COL_V; w = wv; out = g_v; chans = 512;  do_l2 = 0; scale = 1.f; }

    float acc = 0.f;
    #pragma unroll
    for (int j = 0; j < 4; j++) {
        int sl = l + j - 3;
        if (sl >= 0) acc += in[(size_t)(row + j - 3) * NCAT + c] * w[c * 4 + j];
    }
    float yv = acc / (1.f + expf(-acc));

    if (do_l2) {
        __shared__ float smr[4];
        float ss = yv * yv;
        #pragma unroll
        for (int off = 16; off > 0; off >>= 1)
            ss += __shfl_xor_sync(0xffffffffu, ss, off);
        if ((tid & 31) == 0) smr[tid >> 5] = ss;
        __syncthreads();
        float tot = smr[0] + smr[1] + smr[2] + smr[3];
        yv *= rsqrtf(tot + 1e-6f) * scale;
    }
    out[(size_t)row * chans + c] = yv;
}

// ---------------------------------------------------------------------------
// Chunked WY gated delta-rule. 128 CTAs = (b,h) x v-half, 512 threads.
// Round 16: 16 warps/CTA (4/SMSP) for latency hiding; same math/layout.
// ---------------------------------------------------------------------------
#define R_ST    0
#define R_STHI  32768
#define R_STLO  50176
#define R_KHI   67584      // also fp32 stage [64][128]
#define R_KLO   84992
#define R_QH    102400
#define R_SCR   119808     // KK fp32[64][64] | Kths fp16[128][72] | MU fp32
#define R_AF    138240     // QK temp -> A fp32 [64][64]
#define R_MH    154624     // M fp16 [64][72]
#define R_QS    163840     // QS fp32 [64][64]
#define R_U     180224     // KS -> RHS -> U fp32 [64][64]
#define R_UTHI  196608     // fp16 [64][72]  (U^T hi)
#define R_UTLO  205824
#define R_CUM   215040
#define R_BETA  215296
#define R_LAM   215552
#define R_RL    215808
#define R_TOTAL 216064

#define RW_NT   512
#define RW_NW   16

__device__ __forceinline__ void gemm_sm(
    float* dst, int ldd, int M, int N, int Kd, int lda, int ldb,
    const __half* A0, const __half* B0,
    const __half* A1, const __half* B1,
    const __half* A2, const __half* B2, int npass)
{
    const int tid  = threadIdx.x;
    const int wid  = tid >> 5;
    const int lane = tid & 31;
    const int ntile = (M >> 4) * (N >> 3);
    const int arow = lane & 15;
    const int acol = (lane >> 4) << 3;
    const int brow = lane & 7;
    const int bcol = ((lane >> 3) & 1) << 3;

    for (int tile = wid; tile < ntile; tile += RW_NW) {
        const int tm = tile / (N >> 3);
        const int tn = tile % (N >> 3);
        float acc[4] = {0.f, 0.f, 0.f, 0.f};
        #pragma unroll 1
        for (int p = 0; p < npass; p++) {
            const __half* A = (p == 0) ? A0 : (p == 1) ? A1 : A2;
            const __half* B = (p == 0) ? B0 : (p == 1) ? B1 : B2;
            uint32_t abase = smem_to_u32(A) +
                (uint32_t)(((tm * 16 + arow) * lda + acol) * 2);
            uint32_t bbase = smem_to_u32(B) +
                (uint32_t)(((tn * 8 + brow) * ldb + bcol) * 2);
            for (int k = 0; k < Kd; k += 16) {
                uint32_t a[4], b[2];
                LDSM4(a, abase + (uint32_t)(k * 2));
                LDSM2(b, bbase + (uint32_t)(k * 2));
                MMA16816F(acc, a, b);
            }
        }
        const int g  = lane >> 2;
        const int t2 = (lane & 3) << 1;
        const int r = tm * 16 + g;
        const int c = tn * 8 + t2;
        dst[r * ldd + c]           = acc[0];
        dst[r * ldd + c + 1]       = acc[1];
        dst[(r + 8) * ldd + c]     = acc[2];
        dst[(r + 8) * ldd + c + 1] = acc[3];
    }
}

__global__ __launch_bounds__(RW_NT) void recurrence_kernel()
{
    extern __shared__ char sm[];
    float*  St   = (float*)(sm + R_ST);
    __half* Sthi = (__half*)(sm + R_STHI);
    __half* Stlo = (__half*)(sm + R_STLO);
    __half* Khi  = (__half*)(sm + R_KHI);
    __half* Klo  = (__half*)(sm + R_KLO);
    __half* Qh   = (__half*)(sm + R_QH);
    float*  SCRf = (float*)(sm + R_SCR);
    __half* Kths = (__half*)(sm + R_SCR);
    float*  stage= (float*)(sm + R_KHI);
    float*  Af   = (float*)(sm + R_AF);
    __half* Mh   = (__half*)(sm + R_MH);
    float*  QSf  = (float*)(sm + R_QS);
    float*  U    = (float*)(sm + R_U);
    __half* Uthi = (__half*)(sm + R_UTHI);
    __half* Utlo = (__half*)(sm + R_UTLO);
    float*  bet  = (float*)(sm + R_BETA);
    float*  lam  = (float*)(sm + R_LAM);
    float*  rl   = (float*)(sm + R_RL);

    const int bx   = blockIdx.x;
    const int pair = bx >> 1;
    const int vh   = bx & 1;
    const int b    = pair >> 4;
    const int h    = pair & 15;
    const int kh   = h >> 2;
    const int tid  = threadIdx.x;

    // init St and its splits to zero
    for (int i = tid; i < 2048; i += RW_NT) ((float4*)St)[i] = make_float4(0, 0, 0, 0);
    for (int i = tid; i < 4352; i += RW_NT) { ((uint32_t*)Sthi)[i] = 0; ((uint32_t*)Stlo)[i] = 0; }
    __syncthreads();

    for (int ch = 0; ch < 16; ch++) {
        const int s0row = b * SEQ + ch * 64;

        // Ph0: vectorized K hi/lo + Q loads; warp0: scan + tables
        for (int i = tid; i < 2048; i += RW_NT) {
            int r = i >> 5, d = (i & 31) << 2;
            float4 kv = *(const float4*)&g_k[(size_t)(s0row + r) * 512 + kh * 128 + d];
            float4 qv = *(const float4*)&g_q[(size_t)(s0row + r) * 2048 + h * 128 + d];
            uint2 hi, lo;
            split4(kv, hi, lo);
            *(uint2*)&Khi[r * 136 + d] = hi;
            *(uint2*)&Klo[r * 136 + d] = lo;
            *(uint2*)&Qh[r * 136 + d] = pack4h(qv.x, qv.y, qv.z, qv.w);
        }
        if (tid < 32) {
            float a  = g_gd[(size_t)(s0row + tid) * NH + h];
            float c2 = g_gd[(size_t)(s0row + 32 + tid) * NH + h];
            bet[tid]      = g_beta[(size_t)(s0row + tid) * NH + h];
            bet[tid + 32] = g_beta[(size_t)(s0row + 32 + tid) * NH + h];
            #pragma unroll
            for (int off = 1; off < 32; off <<= 1) {
                float t1 = __shfl_up_sync(0xffffffffu, a, off);
                float t2 = __shfl_up_sync(0xffffffffu, c2, off);
                if (tid >= off) { a += t1; c2 += t2; }
            }
            c2 += __shfl_sync(0xffffffffu, a, 31);
            lam[tid] = expf(a);       rl[tid] = expf(-a);
            lam[tid + 32] = expf(c2); rl[tid + 32] = expf(-c2);
        }
        __syncthreads();

        // G4: all four GEMMs in one phase
        gemm_sm(SCRf, 64, 64, 64, 128, 136, 136, Khi, Khi, Khi, Klo, Klo, Khi, 3); // KK
        gemm_sm(Af,   64, 64, 64, 128, 136, 136, Qh,  Khi, Qh,  Klo, 0, 0, 2);     // QK (temp)
        gemm_sm(U,    64, 64, 64, 128, 136, 136, Khi, Sthi, Khi, Stlo, Klo, Sthi, 3); // KS
        gemm_sm(QSf,  64, 64, 64, 128, 136, 136, Qh,  Sthi, Qh,  Stlo, 0, 0, 2);    // QS
        __syncthreads();

        // PhT: A/M transforms + RHS, vectorized
        for (int i = tid; i < 1024; i += RW_NT) {
            int t = i >> 4, s = (i & 15) << 2;
            float4 kk = *(float4*)&SCRf[t * 64 + s];
            float4 qk = *(float4*)&Af[t * 64 + s];
            float4 rls = *(float4*)&rl[s];
            float lt = lam[t], bt = bet[t];
            float r0 = lt * rls.x, r1 = lt * rls.y, r2 = lt * rls.z, r3 = lt * rls.w;
            float4 av;
            av.x = (s + 0 < t) ? bt * r0 * kk.x : 0.f;
            av.y = (s + 1 < t) ? bt * r1 * kk.y : 0.f;
            av.z = (s + 2 < t) ? bt * r2 * kk.z : 0.f;
            av.w = (s + 3 < t) ? bt * r3 * kk.w : 0.f;
            *(uint2*)&Mh[t * 72 + s] = pack4h(
                (s + 0 <= t) ? r0 * qk.x : 0.f, (s + 1 <= t) ? r1 * qk.y : 0.f,
                (s + 2 <= t) ? r2 * qk.z : 0.f, (s + 3 <= t) ? r3 * qk.w : 0.f);
            *(float4*)&Af[t * 64 + s] = av;
        }
        for (int i = tid; i < 1024; i += RW_NT) {
            int t = i >> 4, c = (i & 15) << 2;
            float4 v4 = *(const float4*)&g_v[(size_t)(s0row + t) * 512 + kh * 128 + vh * 64 + c];
            float4 u4 = *(float4*)&U[t * 64 + c];
            float lt = lam[t], bt = bet[t];
            u4.x = bt * (v4.x - lt * u4.x);
            u4.y = bt * (v4.y - lt * u4.y);
            u4.z = bt * (v4.z - lt * u4.z);
            u4.w = bt * (v4.w - lt * u4.w);
            *(float4*)&U[t * 64 + c] = u4;
        }
        __syncthreads();

        // Ph5: forward substitution (I+A)U = RHS ; 8 threads/column
        {
            const int col = tid >> 3, par = tid & 7;
            for (int r = 1; r < 64; r++) {
                float p = 0.f;
                for (int s = par; s < r; s += 8)
                    p = fmaf(Af[r * 64 + s], U[s * 64 + col], p);
                p += __shfl_xor_sync(0xffffffffu, p, 1);
                p += __shfl_xor_sync(0xffffffffu, p, 2);
                p += __shfl_xor_sync(0xffffffffu, p, 4);
                if (par == 0) U[r * 64 + col] -= p;
                __syncwarp();
            }
        }
        __syncthreads();

        // Ph6: U^T hi/lo split + Kths
        {
            float lC = lam[63];
            for (int i = tid; i < 1024; i += RW_NT) {
                int s = i >> 4, c = (i & 15) << 2;
                float4 u4 = *(float4*)&U[s * 64 + c];
                #pragma unroll
                for (int j = 0; j < 4; j++) {
                    float u = (j == 0) ? u4.x : (j == 1) ? u4.y : (j == 2) ? u4.z : u4.w;
                    __half uh = __float2half_rn(u);
                    Uthi[(c + j) * 72 + s] = uh;
                    Utlo[(c + j) * 72 + s] = __float2half_rn(u - __half2float(uh));
                }
            }
            for (int i = tid; i < 2048; i += RW_NT) {
                int s = i >> 5, d = (i & 31) << 2;
                uint2 khv = *(uint2*)&Khi[s * 136 + d];
                uint2 klv = *(uint2*)&Klo[s * 136 + d];
                __half2 kh0 = *(__half2*)&khv.x, kh1 = *(__half2*)&khv.y;
                __half2 kl0 = *(__half2*)&klv.x, kl1 = *(__half2*)&klv.y;
                float sc = lC * rl[s];
                Kths[(d + 0) * 72 + s] = __float2half_rn(sc * (__half2float(kh0.x) + __half2float(kl0.x)));
                Kths[(d + 1) * 72 + s] = __float2half_rn(sc * (__half2float(kh0.y) + __half2float(kl0.y)));
                Kths[(d + 2) * 72 + s] = __float2half_rn(sc * (__half2float(kh1.x) + __half2float(kl1.x)));
                Kths[(d + 3) * 72 + s] = __float2half_rn(sc * (__half2float(kh1.y) + __half2float(kl1.y)));
            }
        }
        __syncthreads();

        // Ph7: state GEMM -> stage (overwrites Khi/Klo region)
        gemm_sm(stage, 128, 64, 128, 64, 72, 72, Uthi, Kths, Utlo, Kths, 0, 0, 2);
        __syncthreads();

        // Ph8: MU GEMM -> SCRf  +  fused St update + hi/lo split
        gemm_sm(SCRf, 64, 64, 64, 64, 72, 72, Mh, Uthi, Mh, Utlo, 0, 0, 2);
        {
            float lC = lam[63];
            for (int i = tid; i < 2048; i += RW_NT) {
                int off = i << 2;
                float4 st4 = *(float4*)&St[off];
                float4 sg4 = *(float4*)&stage[off];
                st4.x = lC * st4.x + sg4.x;
                st4.y = lC * st4.y + sg4.y;
                st4.z = lC * st4.z + sg4.z;
                st4.w = lC * st4.w + sg4.w;
                *(float4*)&St[off] = st4;
                int r = off >> 7, d = off & 127;
                uint2 hi, lo;
                split4(st4, hi, lo);
                *(uint2*)&Sthi[r * 136 + d] = hi;
                *(uint2*)&Stlo[r * 136 + d] = lo;
            }
        }
        __syncthreads();

        // Ph9: output o = lam_t*QS + MU
        for (int i = tid; i < 1024; i += RW_NT) {
            int t = i >> 4, c = (i & 15) << 2;
            float4 qs = *(float4*)&QSf[t * 64 + c];
            float4 mu = *(float4*)&SCRf[t * 64 + c];
            float lt = lam[t];
            float4 o;
            o.x = lt * qs.x + mu.x; o.y = lt * qs.y + mu.y;
            o.z = lt * qs.z + mu.z; o.w = lt * qs.w + mu.w;
            *(float4*)&g_o[(size_t)(s0row + t) * 2048 + h * 128 + vh * 64 + c] = o;
        }
        __syncthreads();
    }
}

// ---------------------------------------------------------------------------
// FusedRMSNormGated -> fp16
// ---------------------------------------------------------------------------
__global__ __launch_bounds__(128) void rmsgate_kernel(
    const float* __restrict__ xcat, const float* __restrict__ w)
{
    const int row = blockIdx.x;
    const int h   = blockIdx.y;
    const int t   = threadIdx.x;

    const size_t idx = (size_t)(row * NH + h) * DHEAD + t;
    float o = g_o[idx];

    float ss = o * o;
    #pragma unroll
    for (int off = 16; off > 0; off >>= 1)
        ss += __shfl_xor_sync(0xffffffffu, ss, off);
    __shared__ float sm[4];
    if ((t & 31) == 0) sm[t >> 5] = ss;
    __syncthreads();
    float tot = sm[0] + sm[1] + sm[2] + sm[3];
    float r = rsqrtf(tot * (1.f / 128.f) + 1e-5f);

    float gate = xcat[(size_t)row * NCAT + COL_G + h * DHEAD + t];
    float sg   = gate / (1.f + expf(-gate));
    float val  = o * r * w[t] * sg;
    g_of[(size_t)row * DH_ + h * DHEAD + t] = __float2half_rn(val);
}

// ---------------------------------------------------------------------------
// Launch: prep(0), gemm1(1), conv_betag(2), recurrence(3 <- ncu capture),
//         rmsgate(4), gemm1-out(5)
// ---------------------------------------------------------------------------
extern "C" void kernel_launch(void* const* d_in, const int* in_sizes, int n_in,
                              void* d_out, int out_size)
{
    (void)in_sizes; (void)n_in; (void)out_size;
    const float* x     = (const float*)d_in[0];
    const float* Wq    = (const float*)d_in[1];
    const float* Wk    = (const float*)d_in[2];
    const float* Wv    = (const float*)d_in[3];
    const float* Wb    = (const float*)d_in[4];
    const float* Wgk   = (const float*)d_in[5];
    const float* A_log = (const float*)d_in[6];
    const float* dt_b  = (const float*)d_in[7];
    const float* convq = (const float*)d_in[8];
    const float* convk = (const float*)d_in[9];
    const float* convv = (const float*)d_in[10];
    const float* Wg    = (const float*)d_in[11];
    const float* onw   = (const float*)d_in[12];
    const float* Wo    = (const float*)d_in[13];
    float* out = (float*)d_out;

    cudaFuncSetAttribute(gemm1, cudaFuncAttributeMaxDynamicSharedMemorySize, SM1);
    cudaFuncSetAttribute(recurrence_kernel,
                         cudaFuncAttributeMaxDynamicSharedMemorySize, R_TOTAL);

    float *p_xcat;
    __half *p_xhi, *p_of, *p_wcat, *p_wot;
    cudaGetSymbolAddress((void**)&p_xcat, g_xcat);
    cudaGetSymbolAddress((void**)&p_xhi, g_xhi);
    cudaGetSymbolAddress((void**)&p_of,  g_of);
    cudaGetSymbolAddress((void**)&p_wcat, g_wcat);
    cudaGetSymbolAddress((void**)&p_wot,  g_wot);

    // 0) tof16 + weight transposes
    prep_kernel<<<PREP_NB, 256>>>(x, Wq, Wk, Wv, Wg, Wo, p_xhi, p_wcat, p_wot);
    // 1) fused projection GEMM
    gemm1<<<dim3(NCAT / 128, 32), 256, SM1>>>(p_xhi, p_wcat, p_xcat, NCAT, DH_);
    // 2) convs + beta/g
    conv_betag<<<dim3(ROWS, 25), 128>>>(p_xcat, x, convq, convk, convv,
                                        Wb, Wgk, A_log, dt_b);
    // 3) chunked recurrence   <-- ncu capture target
    recurrence_kernel<<<128, RW_NT, R_TOTAL>>>();
    // 4) gated rmsnorm (-> fp16)
    rmsgate_kernel<<<dim3(ROWS, 16), 128>>>(p_xcat, onw);
    // 5) output projection
    gemm1<<<dim3(16, 32), 256, SM1>>>(p_of, p_wot, out, 2048, DH_);
}

// round 17
// speedup vs baseline: 1.1312x; 1.1312x over previous
#include <cuda_runtime.h>
#include <cuda_fp16.h>
#include <math.h>
#include <stdint.h>

// ---------------------------------------------------------------------------
// Problem constants: B=4, L=1024, DH=2048, D=128, HQ=16, HK=HV=4, H=16, K=4
// ---------------------------------------------------------------------------
#define ROWS 4096
#define DH_  2048
#define DHEAD 128
#define NH   16
#define NHK  4
#define SEQ  1024
#define NCAT 5120
#define COL_K 2048
#define COL_V 2560
#define COL_G 3072

// ---------------- device scratch (allocation-free rule) --------------------
__device__ float g_xcat[ROWS * NCAT];
__device__ float g_q [ROWS * DH_];
__device__ float g_k [ROWS * 512];
__device__ float g_v [ROWS * 512];
__device__ float g_beta[ROWS * NH];
__device__ float g_gd  [ROWS * NH];      // log decay g (<= 0)
__device__ float g_o [ROWS * DH_];

__device__ __align__(256) __half g_xhi[ROWS * DH_];
__device__ __align__(256) __half g_of [ROWS * DH_];
__device__ __align__(256) __half g_wcat[NCAT * DH_];
__device__ __align__(256) __half g_wot[DH_ * DH_];

// ---------------------------------------------------------------------------
// PTX helpers
// ---------------------------------------------------------------------------
__device__ __forceinline__ uint32_t smem_to_u32(const void* p) {
    uint32_t a;
    asm("{ .reg .u64 t; cvta.to.shared.u64 t, %1; cvt.u32.u64 %0, t; }"
        : "=r"(a) : "l"(p));
    return a;
}
__device__ __forceinline__ void cp16(uint32_t s, const void* g) {
    asm volatile("cp.async.cg.shared.global [%0], [%1], 16;"
                 :: "r"(s), "l"(g) : "memory");
}
#define CP_COMMIT() asm volatile("cp.async.commit_group;" ::: "memory")

#define LDSM4(d, addr) \
    asm volatile("ldmatrix.sync.aligned.m8n8.x4.shared.b16 {%0,%1,%2,%3}, [%4];" \
        : "=r"((d)[0]), "=r"((d)[1]), "=r"((d)[2]), "=r"((d)[3]) : "r"(addr))

#define MMA16816F(c, a, b) \
    asm volatile("mma.sync.aligned.m16n8k16.row.col.f32.f16.f16.f32 " \
        "{%0,%1,%2,%3}, {%4,%5,%6,%7}, {%8,%9}, {%0,%1,%2,%3};" \
        : "+f"((c)[0]), "+f"((c)[1]), "+f"((c)[2]), "+f"((c)[3]) \
        : "r"((a)[0]), "r"((a)[1]), "r"((a)[2]), "r"((a)[3]), \
          "r"((b)[0]), "r"((b)[1]))

// pack 4 floats -> 4 fp16 in a uint2 ; and hi/lo split of a float4
__device__ __forceinline__ uint2 pack4h(float a, float b, float c, float d) {
    __half2 p0 = __halves2half2(__float2half_rn(a), __float2half_rn(b));
    __half2 p1 = __halves2half2(__float2half_rn(c), __float2half_rn(d));
    uint2 u;
    u.x = *(uint32_t*)&p0;
    u.y = *(uint32_t*)&p1;
    return u;
}
__device__ __forceinline__ void split4(float4 v, uint2& hi, uint2& lo) {
    __half h0 = __float2half_rn(v.x), h1 = __float2half_rn(v.y);
    __half h2 = __float2half_rn(v.z), h3 = __float2half_rn(v.w);
    hi = pack4h(v.x, v.y, v.z, v.w);
    lo = pack4h(v.x - __half2float(h0), v.y - __half2float(h1),
                v.z - __half2float(h2), v.w - __half2float(h3));
}

// ---------------------------------------------------------------------------
// prep: blocks [0,16384) x->fp16 ; [16384,30720) weight transposes
// ---------------------------------------------------------------------------
#define PREP_T0 16384
#define PREP_NB 30720

__global__ __launch_bounds__(256) void prep_kernel(
    const float* __restrict__ x,
    const float* __restrict__ Wq, const float* __restrict__ Wk,
    const float* __restrict__ Wv, const float* __restrict__ Wg,
    const float* __restrict__ Wo,
    __half* __restrict__ xhi, __half* __restrict__ wcat, __half* __restrict__ wot)
{
    __shared__ float t[32][33];
    const int blk = blockIdx.x;
    const int tid = threadIdx.x;

    if (blk < PREP_T0) {
        int i = blk * 256 + tid;
        float2 v = ((const float2*)x)[i];
        ((__half2*)xhi)[i] = __halves2half2(__float2half_rn(v.x), __float2half_rn(v.y));
        return;
    }
    const int idx = blk - PREP_T0;
    const float* W; __half* T; int N, bx, by;
    if (idx < 4096)        { W = Wq; T = wcat;                        N = 2048; int l = idx;         bx = l & 63; by = l >> 6; }
    else if (idx < 5120)   { W = Wk; T = wcat + (size_t)COL_K * DH_;  N =  512; int l = idx - 4096;  bx = l & 15; by = l >> 4; }
    else if (idx < 6144)   { W = Wv; T = wcat + (size_t)COL_V * DH_;  N =  512; int l = idx - 5120;  bx = l & 15; by = l >> 4; }
    else if (idx < 10240)  { W = Wg; T = wcat + (size_t)COL_G * DH_;  N = 2048; int l = idx - 6144;  bx = l & 63; by = l >> 6; }
    else                   { W = Wo; T = wot;                         N = 2048; int l = idx - 10240; bx = l & 63; by = l >> 6; }
    bx <<= 5; by <<= 5;
    const int tx = tid & 31, ty = tid >> 5;
    #pragma unroll
    for (int i = 0; i < 32; i += 8)
        t[ty + i][tx] = W[(size_t)(by + ty + i) * N + bx + tx];
    __syncthreads();
    #pragma unroll
    for (int i = 0; i < 32; i += 8)
        T[(size_t)(bx + ty + i) * DH_ + by + tx] = __float2half_rn(t[tx][ty + i]);
}

// ---------------------------------------------------------------------------
// 1-pass fp16 GEMM (proven): C = A @ B^T
// ---------------------------------------------------------------------------
#define ST1 32768
#define SM1 (3 * ST1)

__global__ __launch_bounds__(256, 2) void gemm1(
    const __half* __restrict__ A, const __half* __restrict__ B,
    float* __restrict__ C, int N, int K)
{
    extern __shared__ char smem[];
    const uint32_t sb = smem_to_u32(smem);
    const int tid  = threadIdx.x;
    const int lane = tid & 31;
    const int wid  = tid >> 5;
    const int wm   = wid & 1;
    const int wn   = wid >> 1;
    const int brow = blockIdx.y * 128;
    const int bcol = blockIdx.x * 128;
    const size_t K2 = (size_t)K * 2;

    uint32_t swo[4];
    size_t   ga[4], gb[4];
    #pragma unroll
    for (int i = 0; i < 4; i++) {
        int c  = tid + (i << 8);
        int r  = c >> 3, ch = c & 7;
        swo[i] = (uint32_t)(r * 128 + ((ch ^ (r & 7)) << 4));
        ga[i]  = (size_t)(brow + r) * K2 + (size_t)(ch << 4);
        gb[i]  = (size_t)(bcol + r) * K2 + (size_t)(ch << 4);
    }

    const int NK = K >> 6;
    #pragma unroll
    for (int pf = 0; pf < 2; pf++) {
        uint32_t s0 = sb + pf * ST1;
        size_t ko = (size_t)pf << 7;
        #pragma unroll
        for (int i = 0; i < 4; i++) {
            cp16(s0 +     0 + swo[i], (const char*)A + ga[i] + ko);
            cp16(s0 + 16384 + swo[i], (const char*)B + gb[i] + ko);
        }
        CP_COMMIT();
    }

    float acc[4][4][4];
    #pragma unroll
    for (int mi = 0; mi < 4; mi++)
        #pragma unroll
        for (int ni = 0; ni < 4; ni++)
            #pragma unroll
            for (int j = 0; j < 4; j++) acc[mi][ni][j] = 0.f;

    int st_load = 2, st_cmp = 0;
    for (int kt = 0; kt < NK; kt++) {
        if (kt + 2 < NK) {
            uint32_t s0 = sb + st_load * ST1;
            size_t ko = (size_t)(kt + 2) << 7;
            #pragma unroll
            for (int i = 0; i < 4; i++) {
                cp16(s0 +     0 + swo[i], (const char*)A + ga[i] + ko);
                cp16(s0 + 16384 + swo[i], (const char*)B + gb[i] + ko);
            }
            CP_COMMIT();
            if (++st_load == 3) st_load = 0;
        }
        int ahead = NK - 1 - kt; if (ahead > 2) ahead = 2;
        if (ahead == 2)      asm volatile("cp.async.wait_group 2;" ::: "memory");
        else if (ahead == 1) asm volatile("cp.async.wait_group 1;" ::: "memory");
        else                 asm volatile("cp.async.wait_group 0;" ::: "memory");
        __syncthreads();

        const uint32_t sa = sb + st_cmp * ST1;
        #pragma unroll
        for (int ks = 0; ks < 4; ks++) {
            uint32_t ah[4][4];
            const int chA = (ks << 1) + (lane >> 4);
            #pragma unroll
            for (int mi = 0; mi < 4; mi++) {
                int r = wm * 64 + mi * 16 + (lane & 15);
                uint32_t ad = sa + (uint32_t)(r * 128 + ((chA ^ (r & 7)) << 4));
                LDSM4(ah[mi], ad);
            }
            uint32_t bh[4][2];
            #pragma unroll
            for (int nb = 0; nb < 2; nb++) {
                int r = wn * 32 + nb * 16 + (lane & 15);
                uint32_t bd = sa + 16384u + (uint32_t)(r * 128 + ((chA ^ (r & 7)) << 4));
                uint32_t d[4];
                LDSM4(d, bd);
                bh[2*nb][0] = d[0];   bh[2*nb][1] = d[2];
                bh[2*nb+1][0] = d[1]; bh[2*nb+1][1] = d[3];
            }
            #pragma unroll
            for (int mi = 0; mi < 4; mi++)
                #pragma unroll
                for (int ni = 0; ni < 4; ni++)
                    MMA16816F(acc[mi][ni], ah[mi], bh[ni]);
        }
        __syncthreads();
        if (++st_cmp == 3) st_cmp = 0;
    }

    #pragma unroll
    for (int mi = 0; mi < 4; mi++) {
        int r0 = brow + wm * 64 + mi * 16 + (lane >> 2);
        #pragma unroll
        for (int ni = 0; ni < 4; ni++) {
            int c0 = bcol + wn * 32 + ni * 8 + ((lane & 3) << 1);
            *(float2*)&C[(size_t)r0 * N + c0] =
                make_float2(acc[mi][ni][0], acc[mi][ni][1]);
            *(float2*)&C[(size_t)(r0 + 8) * N + c0] =
                make_float2(acc[mi][ni][2], acc[mi][ni][3]);
        }
    }
}

// ---------------------------------------------------------------------------
// conv + betag: grid (4096, 25). y==24: beta / g (log decay, fp32 exact)
// ---------------------------------------------------------------------------
__global__ __launch_bounds__(128) void conv_betag(
    const float* __restrict__ xcat, const float* __restrict__ x,
    const float* __restrict__ wq, const float* __restrict__ wk,
    const float* __restrict__ wv,
    const float* __restrict__ Wb, const float* __restrict__ Wgk,
    const float* __restrict__ A_log, const float* __restrict__ dt_bias)
{
    __shared__ float xs[DH_];
    const int row = blockIdx.x;
    const int y   = blockIdx.y;
    const int tid = threadIdx.x;

    if (y == 24) {
        const float4* xin = (const float4*)(x + (size_t)row * DH_);
        float4* xs4 = (float4*)xs;
        for (int i = tid; i < DH_ / 4; i += 128) xs4[i] = xin[i];
        __syncthreads();
        const int o = tid >> 2;
        const int j = tid & 3;
        const int col = o & 15;
        const float* W = (o < 16) ? Wb : Wgk;
        float s = 0.f;
        #pragma unroll 4
        for (int k = j; k < DH_; k += 4)
            s = fmaf(xs[k], W[k * NH + col], s);
        s += __shfl_xor_sync(0xffffffffu, s, 1);
        s += __shfl_xor_sync(0xffffffffu, s, 2);
        if (j == 0) {
            if (o < 16) {
                g_beta[row * NH + col] = 1.f / (1.f + expf(-s));
            } else {
                float xg = s + dt_bias[col];
                float sp = (xg > 15.f) ? xg : log1pf(expf(xg));
                g_gd[row * NH + col] = -expf(A_log[col]) * sp;   // log decay
            }
        }
        return;
    }

    const int l = row & (SEQ - 1);
    const float* in; const float* w; float* out;
    int c, chans, do_l2; float scale;
    if (y < 16)      { c = y * DHEAD + tid;        in = xcat;         w = wq; out = g_q; chans = 2048; do_l2 = 1; scale = 0.08838834764831845f; }
    else if (y < 20) { c = (y - 16) * DHEAD + tid; in = xcat + COL_K; w = wk; out = g_k; chans = 512;  do_l2 = 1; scale = 1.f; }
    else             { c = (y - 20) * DHEAD + tid; in = xcat + COL_V; w = wv; out = g_v; chans = 512;  do_l2 = 0; scale = 1.f; }

    float acc = 0.f;
    #pragma unroll
    for (int j = 0; j < 4; j++) {
        int sl = l + j - 3;
        if (sl >= 0) acc += in[(size_t)(row + j - 3) * NCAT + c] * w[c * 4 + j];
    }
    float yv = acc / (1.f + expf(-acc));

    if (do_l2) {
        __shared__ float smr[4];
        float ss = yv * yv;
        #pragma unroll
        for (int off = 16; off > 0; off >>= 1)
            ss += __shfl_xor_sync(0xffffffffu, ss, off);
        if ((tid & 31) == 0) smr[tid >> 5] = ss;
        __syncthreads();
        float tot = smr[0] + smr[1] + smr[2] + smr[3];
        yv *= rsqrtf(tot + 1e-6f) * scale;
    }
    out[(size_t)row * chans + c] = yv;
}

// ---------------------------------------------------------------------------
// Chunked WY gated delta-rule. 128 CTAs = (b,h) x v-half, 256 threads.
// Round 17: gemm_sm with 16x32 warp tiles (3 LDSM4 per 4 MMAs).
// ---------------------------------------------------------------------------
#define R_ST    0
#define R_STHI  32768
#define R_STLO  50176
#define R_KHI   67584      // also fp32 stage [64][128]
#define R_KLO   84992
#define R_QH    102400
#define R_SCR   119808     // KK fp32[64][64] | Kths fp16[128][72] | MU fp32
#define R_AF    138240     // QK temp -> A fp32 [64][64]
#define R_MH    154624     // M fp16 [64][72]
#define R_QS    163840     // QS fp32 [64][64]
#define R_U     180224     // KS -> RHS -> U fp32 [64][64]
#define R_UTHI  196608     // fp16 [64][72]  (U^T hi)
#define R_UTLO  205824
#define R_CUM   215040
#define R_BETA  215296
#define R_LAM   215552
#define R_RL    215808
#define R_TOTAL 216064

// smem GEMM, 16x32 warp tiles: dst[M x N] fp32 = sum_p A_p @ B_p^T
// Per k-strip: 1 LDSM4 (A) + 2 LDSM4 (B, 2 n-groups each) + 4 MMAs.
__device__ __forceinline__ void gemm_sm(
    float* dst, int ldd, int M, int N, int Kd, int lda, int ldb,
    const __half* A0, const __half* B0,
    const __half* A1, const __half* B1,
    const __half* A2, const __half* B2, int npass)
{
    const int tid  = threadIdx.x;
    const int wid  = tid >> 5;
    const int lane = tid & 31;
    const int ntile = (M >> 4) * (N >> 5);
    const int lrow = lane & 15;
    const int lcol = (lane >> 4) << 3;

    for (int tile = wid; tile < ntile; tile += 8) {
        const int tm = tile / (N >> 5);
        const int tn = tile % (N >> 5);
        float acc[4][4];
        #pragma unroll
        for (int ni = 0; ni < 4; ni++)
            #pragma unroll
            for (int j = 0; j < 4; j++) acc[ni][j] = 0.f;

        #pragma unroll 1
        for (int p = 0; p < npass; p++) {
            const __half* A = (p == 0) ? A0 : (p == 1) ? A1 : A2;
            const __half* B = (p == 0) ? B0 : (p == 1) ? B1 : B2;
            uint32_t abase = smem_to_u32(A) +
                (uint32_t)(((tm * 16 + lrow) * lda + lcol) * 2);
            uint32_t b0b = smem_to_u32(B) +
                (uint32_t)(((tn * 32 + lrow) * ldb + lcol) * 2);
            uint32_t b1b = b0b + (uint32_t)(16 * ldb * 2);
            for (int k = 0; k < Kd; k += 16) {
                uint32_t a[4], d0[4], d1[4], b[2];
                LDSM4(a,  abase + (uint32_t)(k * 2));
                LDSM4(d0, b0b   + (uint32_t)(k * 2));
                LDSM4(d1, b1b   + (uint32_t)(k * 2));
                b[0] = d0[0]; b[1] = d0[2]; MMA16816F(acc[0], a, b);
                b[0] = d0[1]; b[1] = d0[3]; MMA16816F(acc[1], a, b);
                b[0] = d1[0]; b[1] = d1[2]; MMA16816F(acc[2], a, b);
                b[0] = d1[1]; b[1] = d1[3]; MMA16816F(acc[3], a, b);
            }
        }
        const int g  = lane >> 2;
        const int t2 = (lane & 3) << 1;
        const int r = tm * 16 + g;
        #pragma unroll
        for (int ni = 0; ni < 4; ni++) {
            const int c = tn * 32 + ni * 8 + t2;
            dst[r * ldd + c]           = acc[ni][0];
            dst[r * ldd + c + 1]       = acc[ni][1];
            dst[(r + 8) * ldd + c]     = acc[ni][2];
            dst[(r + 8) * ldd + c + 1] = acc[ni][3];
        }
    }
}

__global__ __launch_bounds__(256) void recurrence_kernel()
{
    extern __shared__ char sm[];
    float*  St   = (float*)(sm + R_ST);
    __half* Sthi = (__half*)(sm + R_STHI);
    __half* Stlo = (__half*)(sm + R_STLO);
    __half* Khi  = (__half*)(sm + R_KHI);
    __half* Klo  = (__half*)(sm + R_KLO);
    __half* Qh   = (__half*)(sm + R_QH);
    float*  SCRf = (float*)(sm + R_SCR);
    __half* Kths = (__half*)(sm + R_SCR);
    float*  stage= (float*)(sm + R_KHI);
    float*  Af   = (float*)(sm + R_AF);
    __half* Mh   = (__half*)(sm + R_MH);
    float*  QSf  = (float*)(sm + R_QS);
    float*  U    = (float*)(sm + R_U);
    __half* Uthi = (__half*)(sm + R_UTHI);
    __half* Utlo = (__half*)(sm + R_UTLO);
    float*  bet  = (float*)(sm + R_BETA);
    float*  lam  = (float*)(sm + R_LAM);
    float*  rl   = (float*)(sm + R_RL);

    const int bx   = blockIdx.x;
    const int pair = bx >> 1;
    const int vh   = bx & 1;
    const int b    = pair >> 4;
    const int h    = pair & 15;
    const int kh   = h >> 2;
    const int tid  = threadIdx.x;

    // init St and its splits to zero
    for (int i = tid; i < 2048; i += 256) ((float4*)St)[i] = make_float4(0, 0, 0, 0);
    for (int i = tid; i < 4352; i += 256) { ((uint32_t*)Sthi)[i] = 0; ((uint32_t*)Stlo)[i] = 0; }
    __syncthreads();

    for (int ch = 0; ch < 16; ch++) {
        const int s0row = b * SEQ + ch * 64;

        // Ph0: vectorized K hi/lo + Q loads; warp0: scan + tables
        for (int i = tid; i < 2048; i += 256) {
            int r = i >> 5, d = (i & 31) << 2;
            float4 kv = *(const float4*)&g_k[(size_t)(s0row + r) * 512 + kh * 128 + d];
            float4 qv = *(const float4*)&g_q[(size_t)(s0row + r) * 2048 + h * 128 + d];
            uint2 hi, lo;
            split4(kv, hi, lo);
            *(uint2*)&Khi[r * 136 + d] = hi;
            *(uint2*)&Klo[r * 136 + d] = lo;
            *(uint2*)&Qh[r * 136 + d] = pack4h(qv.x, qv.y, qv.z, qv.w);
        }
        if (tid < 32) {
            float a  = g_gd[(size_t)(s0row + tid) * NH + h];
            float c2 = g_gd[(size_t)(s0row + 32 + tid) * NH + h];
            bet[tid]      = g_beta[(size_t)(s0row + tid) * NH + h];
            bet[tid + 32] = g_beta[(size_t)(s0row + 32 + tid) * NH + h];
            #pragma unroll
            for (int off = 1; off < 32; off <<= 1) {
                float t1 = __shfl_up_sync(0xffffffffu, a, off);
                float t2 = __shfl_up_sync(0xffffffffu, c2, off);
                if (tid >= off) { a += t1; c2 += t2; }
            }
            c2 += __shfl_sync(0xffffffffu, a, 31);
            lam[tid] = expf(a);       rl[tid] = expf(-a);
            lam[tid + 32] = expf(c2); rl[tid + 32] = expf(-c2);
        }
        __syncthreads();

        // G4: all four GEMMs in one phase
        gemm_sm(SCRf, 64, 64, 64, 128, 136, 136, Khi, Khi, Khi, Klo, Klo, Khi, 3); // KK
        gemm_sm(Af,   64, 64, 64, 128, 136, 136, Qh,  Khi, Qh,  Klo, 0, 0, 2);     // QK (temp)
        gemm_sm(U,    64, 64, 64, 128, 136, 136, Khi, Sthi, Khi, Stlo, Klo, Sthi, 3); // KS
        gemm_sm(QSf,  64, 64, 64, 128, 136, 136, Qh,  Sthi, Qh,  Stlo, 0, 0, 2);    // QS
        __syncthreads();

        // PhT: A/M transforms + RHS, vectorized
        for (int i = tid; i < 1024; i += 256) {
            int t = i >> 4, s = (i & 15) << 2;
            float4 kk = *(float4*)&SCRf[t * 64 + s];
            float4 qk = *(float4*)&Af[t * 64 + s];
            float4 rls = *(float4*)&rl[s];
            float lt = lam[t], bt = bet[t];
            float r0 = lt * rls.x, r1 = lt * rls.y, r2 = lt * rls.z, r3 = lt * rls.w;
            float4 av;
            av.x = (s + 0 < t) ? bt * r0 * kk.x : 0.f;
            av.y = (s + 1 < t) ? bt * r1 * kk.y : 0.f;
            av.z = (s + 2 < t) ? bt * r2 * kk.z : 0.f;
            av.w = (s + 3 < t) ? bt * r3 * kk.w : 0.f;
            *(uint2*)&Mh[t * 72 + s] = pack4h(
                (s + 0 <= t) ? r0 * qk.x : 0.f, (s + 1 <= t) ? r1 * qk.y : 0.f,
                (s + 2 <= t) ? r2 * qk.z : 0.f, (s + 3 <= t) ? r3 * qk.w : 0.f);
            *(float4*)&Af[t * 64 + s] = av;
        }
        for (int i = tid; i < 1024; i += 256) {
            int t = i >> 4, c = (i & 15) << 2;
            float4 v4 = *(const float4*)&g_v[(size_t)(s0row + t) * 512 + kh * 128 + vh * 64 + c];
            float4 u4 = *(float4*)&U[t * 64 + c];
            float lt = lam[t], bt = bet[t];
            u4.x = bt * (v4.x - lt * u4.x);
            u4.y = bt * (v4.y - lt * u4.y);
            u4.z = bt * (v4.z - lt * u4.z);
            u4.w = bt * (v4.w - lt * u4.w);
            *(float4*)&U[t * 64 + c] = u4;
        }
        __syncthreads();

        // Ph5: forward substitution (I+A)U = RHS
        {
            const int col = tid >> 2, par = tid & 3;
            for (int r = 1; r < 64; r++) {
                float p = 0.f;
                for (int s = par; s < r; s += 4)
                    p = fmaf(Af[r * 64 + s], U[s * 64 + col], p);
                p += __shfl_xor_sync(0xffffffffu, p, 1);
                p += __shfl_xor_sync(0xffffffffu, p, 2);
                if (par == 0) U[r * 64 + col] -= p;
                __syncwarp();
            }
        }
        __syncthreads();

        // Ph6: U^T hi/lo split + Kths
        {
            float lC = lam[63];
            for (int i = tid; i < 1024; i += 256) {
                int s = i >> 4, c = (i & 15) << 2;
                float4 u4 = *(float4*)&U[s * 64 + c];
                #pragma unroll
                for (int j = 0; j < 4; j++) {
                    float u = (j == 0) ? u4.x : (j == 1) ? u4.y : (j == 2) ? u4.z : u4.w;
                    __half uh = __float2half_rn(u);
                    Uthi[(c + j) * 72 + s] = uh;
                    Utlo[(c + j) * 72 + s] = __float2half_rn(u - __half2float(uh));
                }
            }
            for (int i = tid; i < 2048; i += 256) {
                int s = i >> 5, d = (i & 31) << 2;
                uint2 khv = *(uint2*)&Khi[s * 136 + d];
                uint2 klv = *(uint2*)&Klo[s * 136 + d];
                __half2 kh0 = *(__half2*)&khv.x, kh1 = *(__half2*)&khv.y;
                __half2 kl0 = *(__half2*)&klv.x, kl1 = *(__half2*)&klv.y;
                float sc = lC * rl[s];
                Kths[(d + 0) * 72 + s] = __float2half_rn(sc * (__half2float(kh0.x) + __half2float(kl0.x)));
                Kths[(d + 1) * 72 + s] = __float2half_rn(sc * (__half2float(kh0.y) + __half2float(kl0.y)));
                Kths[(d + 2) * 72 + s] = __float2half_rn(sc * (__half2float(kh1.x) + __half2float(kl1.x)));
                Kths[(d + 3) * 72 + s] = __float2half_rn(sc * (__half2float(kh1.y) + __half2float(kl1.y)));
            }
        }
        __syncthreads();

        // Ph7: state GEMM -> stage (overwrites Khi/Klo region)
        gemm_sm(stage, 128, 64, 128, 64, 72, 72, Uthi, Kths, Utlo, Kths, 0, 0, 2);
        __syncthreads();

        // Ph8: MU GEMM -> SCRf  +  fused St update + hi/lo split
        gemm_sm(SCRf, 64, 64, 64, 64, 72, 72, Mh, Uthi, Mh, Utlo, 0, 0, 2);
        {
            float lC = lam[63];
            for (int i = tid; i < 2048; i += 256) {
                int off = i << 2;
                float4 st4 = *(float4*)&St[off];
                float4 sg4 = *(float4*)&stage[off];
                st4.x = lC * st4.x + sg4.x;
                st4.y = lC * st4.y + sg4.y;
                st4.z = lC * st4.z + sg4.z;
                st4.w = lC * st4.w + sg4.w;
                *(float4*)&St[off] = st4;
                int r = off >> 7, d = off & 127;
                uint2 hi, lo;
                split4(st4, hi, lo);
                *(uint2*)&Sthi[r * 136 + d] = hi;
                *(uint2*)&Stlo[r * 136 + d] = lo;
            }
        }
        __syncthreads();

        // Ph9: output o = lam_t*QS + MU
        for (int i = tid; i < 1024; i += 256) {
            int t = i >> 4, c = (i & 15) << 2;
            float4 qs = *(float4*)&QSf[t * 64 + c];
            float4 mu = *(float4*)&SCRf[t * 64 + c];
            float lt = lam[t];
            float4 o;
            o.x = lt * qs.x + mu.x; o.y = lt * qs.y + mu.y;
            o.z = lt * qs.z + mu.z; o.w = lt * qs.w + mu.w;
            *(float4*)&g_o[(size_t)(s0row + t) * 2048 + h * 128 + vh * 64 + c] = o;
        }
        __syncthreads();
    }
}

// ---------------------------------------------------------------------------
// FusedRMSNormGated -> fp16
// ---------------------------------------------------------------------------
__global__ __launch_bounds__(128) void rmsgate_kernel(
    const float* __restrict__ xcat, const float* __restrict__ w)
{
    const int row = blockIdx.x;
    const int h   = blockIdx.y;
    const int t   = threadIdx.x;

    const size_t idx = (size_t)(row * NH + h) * DHEAD + t;
    float o = g_o[idx];

    float ss = o * o;
    #pragma unroll
    for (int off = 16; off > 0; off >>= 1)
        ss += __shfl_xor_sync(0xffffffffu, ss, off);
    __shared__ float sm[4];
    if ((t & 31) == 0) sm[t >> 5] = ss;
    __syncthreads();
    float tot = sm[0] + sm[1] + sm[2] + sm[3];
    float r = rsqrtf(tot * (1.f / 128.f) + 1e-5f);

    float gate = xcat[(size_t)row * NCAT + COL_G + h * DHEAD + t];
    float sg   = gate / (1.f + expf(-gate));
    float val  = o * r * w[t] * sg;
    g_of[(size_t)row * DH_ + h * DHEAD + t] = __float2half_rn(val);
}

// ---------------------------------------------------------------------------
// Launch: prep(0), gemm1(1), conv_betag(2), recurrence(3 <- ncu capture),
//         rmsgate(4), gemm1-out(5)
// ---------------------------------------------------------------------------
extern "C" void kernel_launch(void* const* d_in, const int* in_sizes, int n_in,
                              void* d_out, int out_size)
{
    (void)in_sizes; (void)n_in; (void)out_size;
    const float* x     = (const float*)d_in[0];
    const float* Wq    = (const float*)d_in[1];
    const float* Wk    = (const float*)d_in[2];
    const float* Wv    = (const float*)d_in[3];
    const float* Wb    = (const float*)d_in[4];
    const float* Wgk   = (const float*)d_in[5];
    const float* A_log = (const float*)d_in[6];
    const float* dt_b  = (const float*)d_in[7];
    const float* convq = (const float*)d_in[8];
    const float* convk = (const float*)d_in[9];
    const float* convv = (const float*)d_in[10];
    const float* Wg    = (const float*)d_in[11];
    const float* onw   = (const float*)d_in[12];
    const float* Wo    = (const float*)d_in[13];
    float* out = (float*)d_out;

    cudaFuncSetAttribute(gemm1, cudaFuncAttributeMaxDynamicSharedMemorySize, SM1);
    cudaFuncSetAttribute(recurrence_kernel,
                         cudaFuncAttributeMaxDynamicSharedMemorySize, R_TOTAL);

    float *p_xcat;
    __half *p_xhi, *p_of, *p_wcat, *p_wot;
    cudaGetSymbolAddress((void**)&p_xcat, g_xcat);
    cudaGetSymbolAddress((void**)&p_xhi, g_xhi);
    cudaGetSymbolAddress((void**)&p_of,  g_of);
    cudaGetSymbolAddress((void**)&p_wcat, g_wcat);
    cudaGetSymbolAddress((void**)&p_wot,  g_wot);

    // 0) tof16 + weight transposes
    prep_kernel<<<PREP_NB, 256>>>(x, Wq, Wk, Wv, Wg, Wo, p_xhi, p_wcat, p_wot);
    // 1) fused projection GEMM
    gemm1<<<dim3(NCAT / 128, 32), 256, SM1>>>(p_xhi, p_wcat, p_xcat, NCAT, DH_);
    // 2) convs + beta/g
    conv_betag<<<dim3(ROWS, 25), 128>>>(p_xcat, x, convq, convk, convv,
                                        Wb, Wgk, A_log, dt_b);
    // 3) chunked recurrence   <-- ncu capture target
    recurrence_kernel<<<128, 256, R_TOTAL>>>();
    // 4) gated rmsnorm (-> fp16)
    rmsgate_kernel<<<dim3(ROWS, 16), 128>>>(p_xcat, onw);
    // 5) output projection
    gemm1<<<dim3(16, 32), 256, SM1>>>(p_of, p_wot, out, 2048, DH_);
}